// round 14
// baseline (speedup 1.0000x reference)
#include <cuda_runtime.h>
#include <cuda_bf16.h>
#include <mma.h>
#include <cstdint>

using namespace nvcuda;

#define NN 50000
#define NP 50048              // padded to multiple of 128
#define EE 400000
#define GG 2048
#define HH 4
#define CC 64
#define HC 256
#define IND 29
#define EDD 6
#define NTASK 12
#define ET (EE + NN)

// ---------------- scratch (static device globals) ----------------
__device__ float g_h[NP * HC];             // layer-2 GEMM output
__device__ float g_feat[NP * HC];          // layer-2 final output (pooling)
__device__ __nv_bfloat16 g_fh[NP * HC];    // layer-1 output bf16 hi
__device__ __nv_bfloat16 g_fl[NP * HC];    // bf16 lo
__device__ float g_xa[NP * 128];           // layer-1 x-space aggregate [N,4,32]
__device__ float g_als[NN * HH];
__device__ float g_ald[NN * HH];
__device__ float g_ve1[EDD * HH];
__device__ float g_ve2[EDD * HH];
__device__ float g_self1[HH];
__device__ float g_self2[HH];
__device__ float g_mesum[EDD];             // cleared by k_ve2 each call
__device__ int   g_deg[NN];                // restored to 0 by k_scan each call
__device__ int   g_start[NN + 1];
__device__ int   g_cursor[NN];
__device__ int   g_csr_src[ET];
__device__ float g_ale1[ET * HH];
__device__ float g_ale2[ET * HH];
__device__ __nv_bfloat16 g_w2h[HC * HC];
__device__ __nv_bfloat16 g_w2l[HC * HC];

// ---------------- CSR degree count ----------------
__global__ void k_count(const int* __restrict__ ei) {
    int e = blockIdx.x * blockDim.x + threadIdx.x;
    if (e < EE) atomicAdd(&g_deg[ei[EE + e]], 1);
}

// column sums of edge_attr [E,6] — fully coalesced
#define MS_N (EE * EDD / 4)   // 600000 float4s
__global__ __launch_bounds__(256) void k_meansum(const float* __restrict__ ea) {
    __shared__ float sbin[EDD];
    int tid = threadIdx.x;
    if (tid < EDD) sbin[tid] = 0.0f;
    __syncthreads();
    int t = blockIdx.x * 256 + tid;
    float b0 = 0, b1 = 0, b2 = 0, b3 = 0, b4 = 0, b5 = 0;
    if (t < MS_N) {
        float4 v = ((const float4*)ea)[t];
        switch (t % 3) {
            case 0:  b0 = v.x; b1 = v.y; b2 = v.z; b3 = v.w; break;
            case 1:  b4 = v.x; b5 = v.y; b0 = v.z; b1 = v.w; break;
            default: b2 = v.x; b3 = v.y; b4 = v.z; b5 = v.w; break;
        }
    }
#pragma unroll
    for (int off = 16; off > 0; off >>= 1) {
        b0 += __shfl_down_sync(0xffffffffu, b0, off);
        b1 += __shfl_down_sync(0xffffffffu, b1, off);
        b2 += __shfl_down_sync(0xffffffffu, b2, off);
        b3 += __shfl_down_sync(0xffffffffu, b3, off);
        b4 += __shfl_down_sync(0xffffffffu, b4, off);
        b5 += __shfl_down_sync(0xffffffffu, b5, off);
    }
    if ((tid & 31) == 0) {
        atomicAdd(&sbin[0], b0); atomicAdd(&sbin[1], b1);
        atomicAdd(&sbin[2], b2); atomicAdd(&sbin[3], b3);
        atomicAdd(&sbin[4], b4); atomicAdd(&sbin[5], b5);
    }
    __syncthreads();
    if (tid < EDD && sbin[tid] != 0.0f) atomicAdd(&g_mesum[tid], sbin[tid]);
}

// both layers: collapse We with ae -> ve[6,4]; self-loop ale; clear mesum.
// threads 0-23 -> layer 1 entries, 64-87 -> layer 2 entries.
__global__ void k_ve2(const float* __restrict__ We1, const float* __restrict__ ae1,
                      const float* __restrict__ We2, const float* __restrict__ ae2) {
    int t = threadIdx.x;
    __shared__ float vs1[EDD * HH];
    __shared__ float vs2[EDD * HH];
    if (t < EDD * HH) {
        int j = t / HH, h = t % HH;
        float s = 0.0f;
#pragma unroll
        for (int c = 0; c < CC; c++) s += We1[j * HC + h * CC + c] * ae1[h * CC + c];
        g_ve1[t] = s;
        vs1[t] = s;
    } else if (t >= 64 && t < 64 + EDD * HH) {
        int q = t - 64;
        int j = q / HH, h = q % HH;
        float s = 0.0f;
#pragma unroll
        for (int c = 0; c < CC; c++) s += We2[j * HC + h * CC + c] * ae2[h * CC + c];
        g_ve2[q] = s;
        vs2[q] = s;
    }
    __syncthreads();
    const float inv = 1.0f / (float)EE;
    if (t < HH) {
        float s = 0.0f;
#pragma unroll
        for (int j = 0; j < EDD; j++) s += g_mesum[j] * inv * vs1[j * HH + t];
        g_self1[t] = s;
    } else if (t >= 64 && t < 64 + HH) {
        int h = t - 64;
        float s = 0.0f;
#pragma unroll
        for (int j = 0; j < EDD; j++) s += g_mesum[j] * inv * vs2[j * HH + h];
        g_self2[h] = s;
    }
    __syncthreads();
    if (t >= 32 && t < 32 + EDD) g_mesum[t - 32] = 0.0f;
}

// als/ald = x (N,29) @ (W1 collapsed with as1/ad1) — vsd computed in-block
__global__ __launch_bounds__(256) void k_alsd(const float* __restrict__ x,
                                              const float* __restrict__ W1,
                                              const float* __restrict__ a_s,
                                              const float* __restrict__ a_d) {
    __shared__ float xs[32][IND + 1];
    __shared__ float vs[IND][8];
    int n0 = blockIdx.x * 32;
    int tid = threadIdx.x;
    // in-block vsd: 232 threads each compute one [j][o] entry
    if (tid < IND * 8) {
        int j = tid >> 3, o = tid & 7;
        int h = o & 3;
        const float* a = (o < 4) ? a_s : a_d;
        float s = 0.0f;
#pragma unroll
        for (int c = 0; c < CC; c++) s += __ldg(&W1[j * HC + h * CC + c]) * __ldg(&a[h * CC + c]);
        vs[j][o] = s;
    }
    for (int i = tid; i < 32 * IND; i += 256) {
        int r = i / IND, c = i % IND;
        int n = n0 + r;
        xs[r][c] = (n < NN) ? x[n * IND + c] : 0.0f;
    }
    __syncthreads();
    int r = tid >> 3, o = tid & 7;
    int n = n0 + r;
    if (n >= NN) return;
    float s = 0.0f;
#pragma unroll
    for (int c = 0; c < IND; c++) s += xs[r][c] * vs[c][o];
    if (o < 4) g_als[n * HH + o] = s;
    else       g_ald[n * HH + (o - 4)] = s;
}

// ---------------- CSR scan (+1 self-loop slot; restores deg=0) --------------
__global__ __launch_bounds__(1024) void k_scan() {
    __shared__ int warpsum[32];
    __shared__ int carry;
    int tid = threadIdx.x, lane = tid & 31, wid = tid >> 5;
    if (tid == 0) carry = 0;
    __syncthreads();
    for (int base = 0; base < NN; base += 1024) {
        int i = base + tid;
        int v = 0;
        if (i < NN) {
            v = g_deg[i] + 1;
            g_deg[i] = 0;
        }
        int x = v;
#pragma unroll
        for (int off = 1; off < 32; off <<= 1) {
            int t = __shfl_up_sync(0xffffffffu, x, off);
            if (lane >= off) x += t;
        }
        if (lane == 31) warpsum[wid] = x;
        __syncthreads();
        if (wid == 0) {
            int s = warpsum[lane];
#pragma unroll
            for (int off = 1; off < 32; off <<= 1) {
                int t = __shfl_up_sync(0xffffffffu, s, off);
                if (lane >= off) s += t;
            }
            warpsum[lane] = s;
        }
        __syncthreads();
        int excl = x - v + (wid > 0 ? warpsum[wid - 1] : 0) + carry;
        if (i < NN) { g_start[i] = excl; g_cursor[i] = excl; }
        __syncthreads();
        if (tid == 1023) carry = excl + v;
        __syncthreads();
    }
    if (threadIdx.x == 0) g_start[NN] = carry;
}

// fill: real edges + explicit self-loop entries (R10-proven layout)
__global__ void k_fill(const int* __restrict__ ei, const float* __restrict__ ea) {
    int e = blockIdx.x * blockDim.x + threadIdx.x;
    if (e >= ET) return;
    int src, dst;
    float a1[HH], a2[HH];
    if (e < EE) {
        src = ei[e]; dst = ei[EE + e];
        float er[EDD];
#pragma unroll
        for (int j = 0; j < EDD; j++) er[j] = ea[e * EDD + j];
#pragma unroll
        for (int h = 0; h < HH; h++) {
            float s1 = 0.0f, s2 = 0.0f;
#pragma unroll
            for (int j = 0; j < EDD; j++) {
                s1 += er[j] * __ldg(&g_ve1[j * HH + h]);
                s2 += er[j] * __ldg(&g_ve2[j * HH + h]);
            }
            a1[h] = s1; a2[h] = s2;
        }
    } else {
        src = dst = e - EE;
#pragma unroll
        for (int h = 0; h < HH; h++) {
            a1[h] = __ldg(&g_self1[h]);
            a2[h] = __ldg(&g_self2[h]);
        }
    }
    int pos = atomicAdd(&g_cursor[dst], 1);
    g_csr_src[pos] = src;
    *(float4*)&g_ale1[pos * HH] = make_float4(a1[0], a1[1], a1[2], a1[3]);
    *(float4*)&g_ale2[pos * HH] = make_float4(a2[0], a2[1], a2[2], a2[3]);
}

// convert W2 -> transposed bf16 hi/lo [n][k]
__global__ void k_w2cvt(const float* __restrict__ W2) {
    int i = blockIdx.x * blockDim.x + threadIdx.x;
    if (i >= HC * HC) return;
    int n = i / HC, k = i % HC;
    float v = W2[k * HC + n];
    __nv_bfloat16 hi = __float2bfloat16(v);
    __nv_bfloat16 lo = __float2bfloat16(v - __bfloat162float(hi));
    g_w2h[n * HC + k] = hi;
    g_w2l[n * HC + k] = lo;
}

// ---------------- layer-1 x-space aggregation (R10-proven) ----------------
__global__ __launch_bounds__(256) void k_nodeagg_x(const float* __restrict__ x) {
    int w = (blockIdx.x * blockDim.x + threadIdx.x) >> 5;
    if (w >= NN) return;
    int lane = threadIdx.x & 31;
    int s0 = g_start[w], s1 = g_start[w + 1];
    float4 ald4 = *(const float4*)&g_ald[w * HH];

    float acc0 = 0, acc1 = 0, acc2 = 0, acc3 = 0;
    float den0 = 0, den1 = 0, den2 = 0, den3 = 0;
    for (int p = s0; p < s1; p++) {
        int src = g_csr_src[p];
        float4 als4 = *(const float4*)&g_als[src * HH];
        float4 ale4 = *(const float4*)&g_ale1[p * HH];
        float a0 = als4.x + ald4.x + ale4.x;
        float a1 = als4.y + ald4.y + ale4.y;
        float a2 = als4.z + ald4.z + ale4.z;
        float a3 = als4.w + ald4.w + ale4.w;
        a0 = (a0 > 0.f) ? a0 : 0.2f * a0;
        a1 = (a1 > 0.f) ? a1 : 0.2f * a1;
        a2 = (a2 > 0.f) ? a2 : 0.2f * a2;
        a3 = (a3 > 0.f) ? a3 : 0.2f * a3;
        float e0 = __expf(a0), e1 = __expf(a1), e2 = __expf(a2), e3 = __expf(a3);
        den0 += e0; den1 += e1; den2 += e2; den3 += e3;
        float xv = (lane < IND) ? __ldg(&x[src * IND + lane]) : 0.0f;
        acc0 += xv * e0; acc1 += xv * e1; acc2 += xv * e2; acc3 += xv * e3;
    }
    float* xa = &g_xa[w * 128];
    xa[lane]      = acc0 / (den0 + 1e-16f);
    xa[32 + lane] = acc1 / (den1 + 1e-16f);
    xa[64 + lane] = acc2 / (den2 + 1e-16f);
    xa[96 + lane] = acc3 / (den3 + 1e-16f);
}

// ---------------- layer-1 post-GEMM: out = relu(xagg @ W1_head + b1) --------
__global__ __launch_bounds__(256) void k_l1post(const float* __restrict__ W1,
                                                const float* __restrict__ b1) {
    __shared__ float xs[32][128];
    int n0 = blockIdx.x * 32;
    int tid = threadIdx.x;
    int head = tid >> 6;
    for (int i = tid; i < 32 * 128; i += 256)
        ((float*)xs)[i] = g_xa[n0 * 128 + i];
    float wr[IND];
#pragma unroll
    for (int c = 0; c < IND; c++) wr[c] = __ldg(&W1[c * HC + tid]);
    float bv = __ldg(&b1[tid]);
    __syncthreads();
#pragma unroll 4
    for (int r = 0; r < 32; r++) {
        int n = n0 + r;
        if (n >= NN) break;
        const float* xr = &xs[r][head * 32];
        float s = bv;
#pragma unroll
        for (int c = 0; c < IND; c++) s += xr[c] * wr[c];
        s = fmaxf(s, 0.0f);
        __nv_bfloat16 hb = __float2bfloat16(s);
        __nv_bfloat16 lb = __float2bfloat16(s - __bfloat162float(hb));
        g_fh[n * HC + tid] = hb;
        g_fl[n * HC + tid] = lb;
    }
}

// ---------------- layer-2 GEMM (WMMA bf16 split) + fused attention dots -----
#define WKC 64
#define LDP 72
#define SM_AH 0
#define SM_AL (128 * LDP)
#define SM_BH (2 * 128 * LDP)
#define SM_BL (2 * 128 * LDP + 256 * LDP)
#define SM_TOT ((2 * 128 * LDP + 2 * 256 * LDP) * 2)   // 110592 bytes

__global__ __launch_bounds__(512) void k_gemm_wmma(const float* __restrict__ a_s,
                                                   const float* __restrict__ a_d) {
    extern __shared__ __nv_bfloat16 sm[];
    int tid = threadIdx.x;
    int wid = tid >> 5;
    int lane = tid & 31;
    int wr = wid >> 2;
    int wc = wid & 3;
    int row0 = blockIdx.x * 128;

    wmma::fragment<wmma::accumulator, 16, 16, 16, float> acc[2][4];
#pragma unroll
    for (int mi = 0; mi < 2; mi++)
#pragma unroll
        for (int ni = 0; ni < 4; ni++) wmma::fill_fragment(acc[mi][ni], 0.0f);

    for (int kc = 0; kc < HC / WKC; kc++) {
        int k0 = kc * WKC;
#pragma unroll
        for (int it = 0; it < 2; it++) {
            int g = tid + it * 512;
            int r = g >> 3, q = g & 7;
            int go = (row0 + r) * HC + k0 + q * 8;
            int so = r * LDP + q * 8;
            *(uint4*)&sm[SM_AH + so] = *(const uint4*)&g_fh[go];
            *(uint4*)&sm[SM_AL + so] = *(const uint4*)&g_fl[go];
        }
#pragma unroll
        for (int it = 0; it < 4; it++) {
            int g = tid + it * 512;
            int r = g >> 3, q = g & 7;
            int go = r * HC + k0 + q * 8;
            int so = r * LDP + q * 8;
            *(uint4*)&sm[SM_BH + so] = *(const uint4*)&g_w2h[go];
            *(uint4*)&sm[SM_BL + so] = *(const uint4*)&g_w2l[go];
        }
        __syncthreads();

#pragma unroll
        for (int ks = 0; ks < WKC / 16; ks++) {
            wmma::fragment<wmma::matrix_a, 16, 16, 16, __nv_bfloat16, wmma::row_major> ah[2], al[2];
            wmma::fragment<wmma::matrix_b, 16, 16, 16, __nv_bfloat16, wmma::col_major> bh[4], bl[4];
#pragma unroll
            for (int mi = 0; mi < 2; mi++) {
                int r = (wr * 32 + mi * 16) * LDP + ks * 16;
                wmma::load_matrix_sync(ah[mi], &sm[SM_AH + r], LDP);
                wmma::load_matrix_sync(al[mi], &sm[SM_AL + r], LDP);
            }
#pragma unroll
            for (int ni = 0; ni < 4; ni++) {
                int r = (wc * 64 + ni * 16) * LDP + ks * 16;
                wmma::load_matrix_sync(bh[ni], &sm[SM_BH + r], LDP);
                wmma::load_matrix_sync(bl[ni], &sm[SM_BL + r], LDP);
            }
#pragma unroll
            for (int mi = 0; mi < 2; mi++)
#pragma unroll
                for (int ni = 0; ni < 4; ni++) {
                    wmma::mma_sync(acc[mi][ni], ah[mi], bh[ni], acc[mi][ni]);
                    wmma::mma_sync(acc[mi][ni], ah[mi], bl[ni], acc[mi][ni]);
                    wmma::mma_sync(acc[mi][ni], al[mi], bh[ni], acc[mi][ni]);
                }
        }
        __syncthreads();
    }
#pragma unroll
    for (int mi = 0; mi < 2; mi++) {
        int row = row0 + wr * 32 + mi * 16;
#pragma unroll
        for (int ni = 0; ni < 4; ni++) {
            int col = wc * 64 + ni * 16;
            wmma::store_matrix_sync(&g_h[row * HC + col], acc[mi][ni], HC,
                                    wmma::mem_row_major);
        }
    }
    // ---- fused attention dots on just-produced rows ----
    __syncthreads();
#pragma unroll 1
    for (int r = 0; r < 8; r++) {
        int node = row0 + wid * 8 + r;
        if (node >= NN) break;
        const float* hr = &g_h[node * HC];
        float ps[4] = {0, 0, 0, 0}, pd[4] = {0, 0, 0, 0};
#pragma unroll
        for (int it = 0; it < 8; it++) {
            int j = lane + 32 * it;
            float hv = hr[j];
            ps[it >> 1] += hv * __ldg(&a_s[j]);
            pd[it >> 1] += hv * __ldg(&a_d[j]);
        }
#pragma unroll
        for (int h = 0; h < HH; h++) {
            float v = ps[h], u = pd[h];
#pragma unroll
            for (int off = 16; off > 0; off >>= 1) {
                v += __shfl_down_sync(0xffffffffu, v, off);
                u += __shfl_down_sync(0xffffffffu, u, off);
            }
            if (lane == 0) {
                g_als[node * HH + h] = v;
                g_ald[node * HH + h] = u;
            }
        }
    }
}

// ---------------- layer-2 single-pass aggregate (R10-proven, warp/node) -----
__global__ __launch_bounds__(256) void k_nodeagg(const float* __restrict__ ale,
                                                 const float* __restrict__ b) {
    int w = (blockIdx.x * blockDim.x + threadIdx.x) >> 5;
    if (w >= NN) return;
    int lane = threadIdx.x & 31;
    int head = lane >> 3;
    int colbase = lane * 8;
    int s0 = g_start[w], s1 = g_start[w + 1];
    float ald_h = __ldg(&g_ald[w * HH + head]);

    float den = 0.0f;
    float acc[8] = {0, 0, 0, 0, 0, 0, 0, 0};
    int p = s0;
    for (; p + 1 < s1; p += 2) {
        int sa = g_csr_src[p];
        int sb = g_csr_src[p + 1];
        const float4* ha = (const float4*)&g_h[sa * HC + colbase];
        const float4* hb = (const float4*)&g_h[sb * HC + colbase];
        float aa = __ldg(&g_als[sa * HH + head]) + ald_h + __ldg(&ale[p * HH + head]);
        float ab = __ldg(&g_als[sb * HH + head]) + ald_h + __ldg(&ale[(p + 1) * HH + head]);
        aa = (aa > 0.0f) ? aa : 0.2f * aa;
        ab = (ab > 0.0f) ? ab : 0.2f * ab;
        float exa = __expf(aa), exb = __expf(ab);
        den += exa + exb;
        float4 a0 = ha[0], a1 = ha[1];
        float4 b0 = hb[0], b1 = hb[1];
        acc[0] += a0.x * exa + b0.x * exb; acc[1] += a0.y * exa + b0.y * exb;
        acc[2] += a0.z * exa + b0.z * exb; acc[3] += a0.w * exa + b0.w * exb;
        acc[4] += a1.x * exa + b1.x * exb; acc[5] += a1.y * exa + b1.y * exb;
        acc[6] += a1.z * exa + b1.z * exb; acc[7] += a1.w * exa + b1.w * exb;
    }
    if (p < s1) {
        int sa = g_csr_src[p];
        const float4* ha = (const float4*)&g_h[sa * HC + colbase];
        float aa = __ldg(&g_als[sa * HH + head]) + ald_h + __ldg(&ale[p * HH + head]);
        aa = (aa > 0.0f) ? aa : 0.2f * aa;
        float exa = __expf(aa);
        den += exa;
        float4 a0 = ha[0], a1 = ha[1];
        acc[0] += a0.x * exa; acc[1] += a0.y * exa;
        acc[2] += a0.z * exa; acc[3] += a0.w * exa;
        acc[4] += a1.x * exa; acc[5] += a1.y * exa;
        acc[6] += a1.z * exa; acc[7] += a1.w * exa;
    }
    float inv = 1.0f / (den + 1e-16f);

    float4 bb0 = __ldg((const float4*)&b[colbase]);
    float4 bb1 = __ldg((const float4*)&b[colbase + 4]);
    float4 o0 = make_float4(fmaxf(acc[0] * inv + bb0.x, 0.f),
                            fmaxf(acc[1] * inv + bb0.y, 0.f),
                            fmaxf(acc[2] * inv + bb0.z, 0.f),
                            fmaxf(acc[3] * inv + bb0.w, 0.f));
    float4 o1 = make_float4(fmaxf(acc[4] * inv + bb1.x, 0.f),
                            fmaxf(acc[5] * inv + bb1.y, 0.f),
                            fmaxf(acc[6] * inv + bb1.z, 0.f),
                            fmaxf(acc[7] * inv + bb1.w, 0.f));
    *(float4*)&g_feat[w * HC + colbase] = o0;
    *(float4*)&g_feat[w * HC + colbase + 4] = o1;
}

// ---------------- fused mean-pool + readout ----------------
__device__ __forceinline__ int lowerb(const int* __restrict__ b, int val) {
    int lo = 0, hi = NN;
    while (lo < hi) {
        int mid = (lo + hi) >> 1;
        if (b[mid] < val) lo = mid + 1; else hi = mid;
    }
    return lo;
}

__global__ __launch_bounds__(256) void k_graph(const int* __restrict__ bat,
                                               const float* __restrict__ Wl,
                                               const float* __restrict__ bl,
                                               float* __restrict__ out) {
    int g = (blockIdx.x * blockDim.x + threadIdx.x) >> 5;
    if (g >= GG) return;
    int lane = threadIdx.x & 31;
    int lo = 0, hi = 0;
    if (lane == 0) {
        lo = lowerb(bat, g);
        hi = lowerb(bat, g + 1);
    }
    lo = __shfl_sync(0xffffffffu, lo, 0);
    hi = __shfl_sync(0xffffffffu, hi, 0);
    float acc[8] = {0, 0, 0, 0, 0, 0, 0, 0};
    int colbase = lane * 8;
    for (int i = lo; i < hi; i++) {
        const float4* fp = (const float4*)&g_feat[i * HC + colbase];
        float4 v0 = fp[0], v1 = fp[1];
        acc[0] += v0.x; acc[1] += v0.y; acc[2] += v0.z; acc[3] += v0.w;
        acc[4] += v1.x; acc[5] += v1.y; acc[6] += v1.z; acc[7] += v1.w;
    }
    float inv = 1.0f / fmaxf((float)(hi - lo), 1.0f);
#pragma unroll
    for (int t = 0; t < NTASK; t++) {
        float p = 0.0f;
#pragma unroll
        for (int k = 0; k < 8; k++)
            p += acc[k] * __ldg(&Wl[(colbase + k) * NTASK + t]);
#pragma unroll
        for (int off = 16; off > 0; off >>= 1)
            p += __shfl_xor_sync(0xffffffffu, p, off);
        if (lane == 0) out[g * NTASK + t] = p * inv + bl[t];
    }
}

// ---------------- host orchestration ----------------
static inline int cdiv(int a, int b) { return (a + b - 1) / b; }

extern "C" void kernel_launch(void* const* d_in, const int* in_sizes, int n_in,
                              void* d_out, int out_size) {
    const float* x   = (const float*)d_in[0];
    const int*   ei  = (const int*)d_in[1];
    const float* ea  = (const float*)d_in[2];
    const int*   bat = (const int*)d_in[3];
    const float* W1  = (const float*)d_in[4];
    const float* as1 = (const float*)d_in[5];
    const float* ad1 = (const float*)d_in[6];
    const float* We1 = (const float*)d_in[7];
    const float* ae1 = (const float*)d_in[8];
    const float* b1  = (const float*)d_in[9];
    const float* W2  = (const float*)d_in[10];
    const float* as2 = (const float*)d_in[11];
    const float* ad2 = (const float*)d_in[12];
    const float* We2 = (const float*)d_in[13];
    const float* ae2 = (const float*)d_in[14];
    const float* b2  = (const float*)d_in[15];
    const float* Wl  = (const float*)d_in[16];
    const float* bl  = (const float*)d_in[17];
    float* out = (float*)d_out;

    static cudaStream_t s2 = nullptr, s3 = nullptr;
    static cudaEvent_t ev_fork = nullptr, ev_aux = nullptr, ev_ve = nullptr;
    if (!s2) {
        cudaStreamCreateWithFlags(&s2, cudaStreamNonBlocking);
        cudaStreamCreateWithFlags(&s3, cudaStreamNonBlocking);
        cudaEventCreateWithFlags(&ev_fork, cudaEventDisableTiming);
        cudaEventCreateWithFlags(&ev_aux, cudaEventDisableTiming);
        cudaEventCreateWithFlags(&ev_ve, cudaEventDisableTiming);
        cudaFuncSetAttribute(k_gemm_wmma,
                             cudaFuncAttributeMaxDynamicSharedMemorySize, SM_TOT);
    }

    float* p_ale1; cudaGetSymbolAddress((void**)&p_ale1, g_ale1);
    float* p_ale2; cudaGetSymbolAddress((void**)&p_ale2, g_ale2);

    // ---- fork ----
    cudaEventRecord(ev_fork, 0);
    cudaStreamWaitEvent(s2, ev_fork, 0);
    cudaStreamWaitEvent(s3, ev_fork, 0);

    // s2: als/ald GEMV (vsd computed in-block); W2 bf16 prep
    k_alsd<<<cdiv(NN, 32), 256, 0, s2>>>(x, W1, as1, ad1);
    k_w2cvt<<<cdiv(HC * HC, 256), 256, 0, s2>>>(W2);
    cudaEventRecord(ev_aux, s2);

    // s3: edge-attr mean -> both layers' ve/self in one launch (clears mesum)
    k_meansum<<<cdiv(MS_N, 256), 256, 0, s3>>>(ea);
    k_ve2<<<1, 128, 0, s3>>>(We1, ae1, We2, ae2);
    cudaEventRecord(ev_ve, s3);

    // default: count -> scan (adds +1 self slot, restores deg=0) -> fill
    k_count<<<cdiv(EE, 256), 256>>>(ei);
    k_scan<<<1, 1024>>>();
    cudaStreamWaitEvent(0, ev_ve, 0);
    k_fill<<<cdiv(ET, 256), 256>>>(ei, ea);
    cudaStreamWaitEvent(0, ev_aux, 0);

    // ---- layer 1: aggregate in x-space, then scalar GEMM ----
    k_nodeagg_x<<<cdiv(NN * 32, 256), 256>>>(x);
    k_l1post<<<cdiv(NN, 32), 256>>>(W1, b1);

    // ---- layer 2 (GEMM with fused att dots) ----
    k_gemm_wmma<<<NP / 128, 512, SM_TOT>>>(as2, ad2);
    k_nodeagg<<<cdiv(NN * 32, 256), 256>>>(p_ale2, b2);

    // ---- readout ----
    k_graph<<<cdiv(GG * 32, 256), 256>>>(bat, Wl, bl, out);
}

// round 15
// speedup vs baseline: 1.2053x; 1.2053x over previous
#include <cuda_runtime.h>
#include <cuda_bf16.h>
#include <mma.h>
#include <cstdint>

using namespace nvcuda;

#define NN 50000
#define NP 50048              // padded to multiple of 128
#define EE 400000
#define GG 2048
#define HH 4
#define CC 64
#define HC 256
#define IND 29
#define EDD 6
#define NTASK 12
#define ET (EE + NN)

// ---------------- scratch (static device globals) ----------------
__device__ float g_h[NP * HC];             // layer-2 GEMM output
__device__ float g_feat[NP * HC];          // layer-2 final output (pooling)
__device__ __nv_bfloat16 g_fh[NP * HC];    // layer-1 output bf16 hi
__device__ __nv_bfloat16 g_fl[NP * HC];    // bf16 lo
__device__ float g_xa[NP * 128];           // layer-1 x-space aggregate [N,4,32]
__device__ float g_als[NN * HH];
__device__ float g_ald[NN * HH];
__device__ float g_vsd[IND * 8];           // W1 collapsed with as1/ad1 [29,8]
__device__ float g_ve1[EDD * HH];
__device__ float g_ve2[EDD * HH];
__device__ float g_self1[HH];
__device__ float g_self2[HH];
__device__ float g_mesum[EDD];
__device__ int   g_deg[NN];
__device__ int   g_start[NN + 1];
__device__ int   g_cursor[NN];
__device__ int   g_csr_src[ET];
__device__ float g_ale1[ET * HH];
__device__ float g_ale2[ET * HH];
__device__ __nv_bfloat16 g_w2h[HC * HC];
__device__ __nv_bfloat16 g_w2l[HC * HC];

// ---------------- utility ----------------
__global__ void k_seti(int* p, int n, int v) {
    int i = blockIdx.x * blockDim.x + threadIdx.x;
    if (i < n) p[i] = v;
}
__global__ void k_zero_f(float* p, int n) {
    int i = blockIdx.x * blockDim.x + threadIdx.x;
    if (i < n) p[i] = 0.0f;
}

// degree count: 1 thread per real edge (deg pre-init 1 for self-loop)
__global__ void k_count(const int* __restrict__ ei) {
    int e = blockIdx.x * blockDim.x + threadIdx.x;
    if (e < EE) atomicAdd(&g_deg[ei[EE + e]], 1);
}

// column sums of edge_attr [E,6] — fully coalesced
#define MS_N (EE * EDD / 4)   // 600000 float4s
__global__ __launch_bounds__(256) void k_meansum(const float* __restrict__ ea) {
    __shared__ float sbin[EDD];
    int tid = threadIdx.x;
    if (tid < EDD) sbin[tid] = 0.0f;
    __syncthreads();
    int t = blockIdx.x * 256 + tid;
    float b0 = 0, b1 = 0, b2 = 0, b3 = 0, b4 = 0, b5 = 0;
    if (t < MS_N) {
        float4 v = ((const float4*)ea)[t];
        switch (t % 3) {
            case 0:  b0 = v.x; b1 = v.y; b2 = v.z; b3 = v.w; break;
            case 1:  b4 = v.x; b5 = v.y; b0 = v.z; b1 = v.w; break;
            default: b2 = v.x; b3 = v.y; b4 = v.z; b5 = v.w; break;
        }
    }
#pragma unroll
    for (int off = 16; off > 0; off >>= 1) {
        b0 += __shfl_down_sync(0xffffffffu, b0, off);
        b1 += __shfl_down_sync(0xffffffffu, b1, off);
        b2 += __shfl_down_sync(0xffffffffu, b2, off);
        b3 += __shfl_down_sync(0xffffffffu, b3, off);
        b4 += __shfl_down_sync(0xffffffffu, b4, off);
        b5 += __shfl_down_sync(0xffffffffu, b5, off);
    }
    if ((tid & 31) == 0) {
        atomicAdd(&sbin[0], b0); atomicAdd(&sbin[1], b1);
        atomicAdd(&sbin[2], b2); atomicAdd(&sbin[3], b3);
        atomicAdd(&sbin[4], b4); atomicAdd(&sbin[5], b5);
    }
    __syncthreads();
    if (tid < EDD && sbin[tid] != 0.0f) atomicAdd(&g_mesum[tid], sbin[tid]);
}

// collapse We (ED,HC) with ae (H,C) -> ve[6,4]; also self-loop ale per head
__global__ void k_ve(const float* __restrict__ We, const float* __restrict__ ae,
                     float* __restrict__ ve, float* __restrict__ self) {
    int t = threadIdx.x;
    __shared__ float vs[EDD * HH];
    if (t < EDD * HH) {
        int j = t / HH, h = t % HH;
        float s = 0.0f;
#pragma unroll
        for (int c = 0; c < CC; c++) s += We[j * HC + h * CC + c] * ae[h * CC + c];
        ve[t] = s;
        vs[t] = s;
    }
    __syncthreads();
    if (t < HH) {
        float s = 0.0f;
        const float inv = 1.0f / (float)EE;
#pragma unroll
        for (int j = 0; j < EDD; j++) s += g_mesum[j] * inv * vs[j * HH + t];
        self[t] = s;
    }
}

// collapse W1 (29,256) with as1/ad1 (4,64) -> vsd[29][8] (cols 0-3 = as, 4-7 = ad)
__global__ void k_vsd(const float* __restrict__ W1, const float* __restrict__ a_s,
                      const float* __restrict__ a_d) {
    int t = threadIdx.x;
    if (t >= IND * 8) return;
    int j = t >> 3, o = t & 7;
    int h = o & 3;
    const float* a = (o < 4) ? a_s : a_d;
    float s = 0.0f;
#pragma unroll
    for (int c = 0; c < CC; c++) s += W1[j * HC + h * CC + c] * a[h * CC + c];
    g_vsd[j * 8 + o] = s;
}

// als/ald = x (N,29) @ vsd (29,8): block = 32 nodes, 256 threads
__global__ __launch_bounds__(256) void k_alsd(const float* __restrict__ x) {
    __shared__ float xs[32][IND + 1];
    __shared__ float vs[IND][8];
    int n0 = blockIdx.x * 32;
    int tid = threadIdx.x;
    for (int i = tid; i < 32 * IND; i += 256) {
        int r = i / IND, c = i % IND;
        int n = n0 + r;
        xs[r][c] = (n < NN) ? x[n * IND + c] : 0.0f;
    }
    if (tid < IND * 8) vs[tid >> 3][tid & 7] = g_vsd[tid];
    __syncthreads();
    int r = tid >> 3, o = tid & 7;   // 32 nodes x 8 outputs
    int n = n0 + r;
    if (n >= NN) return;
    float s = 0.0f;
#pragma unroll
    for (int c = 0; c < IND; c++) s += xs[r][c] * vs[c][o];
    if (o < 4) g_als[n * HH + o] = s;
    else       g_ald[n * HH + (o - 4)] = s;
}

// ---------------- CSR scan + fill ----------------
__global__ __launch_bounds__(1024) void k_scan() {
    __shared__ int warpsum[32];
    __shared__ int carry;
    int tid = threadIdx.x, lane = tid & 31, wid = tid >> 5;
    if (tid == 0) carry = 0;
    __syncthreads();
    for (int base = 0; base < NN; base += 1024) {
        int i = base + tid;
        int v = (i < NN) ? g_deg[i] : 0;
        int x = v;
#pragma unroll
        for (int off = 1; off < 32; off <<= 1) {
            int t = __shfl_up_sync(0xffffffffu, x, off);
            if (lane >= off) x += t;
        }
        if (lane == 31) warpsum[wid] = x;
        __syncthreads();
        if (wid == 0) {
            int s = warpsum[lane];
#pragma unroll
            for (int off = 1; off < 32; off <<= 1) {
                int t = __shfl_up_sync(0xffffffffu, s, off);
                if (lane >= off) s += t;
            }
            warpsum[lane] = s;
        }
        __syncthreads();
        int excl = x - v + (wid > 0 ? warpsum[wid - 1] : 0) + carry;
        if (i < NN) { g_start[i] = excl; g_cursor[i] = excl; }
        __syncthreads();
        if (tid == 1023) carry = excl + v;
        __syncthreads();
    }
    if (threadIdx.x == 0) g_start[NN] = carry;
}

__global__ void k_fill(const int* __restrict__ ei, const float* __restrict__ ea) {
    int e = blockIdx.x * blockDim.x + threadIdx.x;
    if (e >= ET) return;
    int src, dst;
    float a1[HH], a2[HH];
    if (e < EE) {
        src = ei[e]; dst = ei[EE + e];
        float er[EDD];
#pragma unroll
        for (int j = 0; j < EDD; j++) er[j] = ea[e * EDD + j];
#pragma unroll
        for (int h = 0; h < HH; h++) {
            float s1 = 0.0f, s2 = 0.0f;
#pragma unroll
            for (int j = 0; j < EDD; j++) {
                s1 += er[j] * __ldg(&g_ve1[j * HH + h]);
                s2 += er[j] * __ldg(&g_ve2[j * HH + h]);
            }
            a1[h] = s1; a2[h] = s2;
        }
    } else {
        src = dst = e - EE;
#pragma unroll
        for (int h = 0; h < HH; h++) {
            a1[h] = __ldg(&g_self1[h]);
            a2[h] = __ldg(&g_self2[h]);
        }
    }
    int pos = atomicAdd(&g_cursor[dst], 1);
    g_csr_src[pos] = src;
    *(float4*)&g_ale1[pos * HH] = make_float4(a1[0], a1[1], a1[2], a1[3]);
    *(float4*)&g_ale2[pos * HH] = make_float4(a2[0], a2[1], a2[2], a2[3]);
}

// convert W2 -> transposed bf16 hi/lo [n][k]
__global__ void k_w2cvt(const float* __restrict__ W2) {
    int i = blockIdx.x * blockDim.x + threadIdx.x;
    if (i >= HC * HC) return;
    int n = i / HC, k = i % HC;
    float v = W2[k * HC + n];
    __nv_bfloat16 hi = __float2bfloat16(v);
    __nv_bfloat16 lo = __float2bfloat16(v - __bfloat162float(hi));
    g_w2h[n * HC + k] = hi;
    g_w2l[n * HC + k] = lo;
}

// ---------------- layer-1 x-space aggregation (single pass) ----------------
__global__ __launch_bounds__(256) void k_nodeagg_x(const float* __restrict__ x) {
    int w = (blockIdx.x * blockDim.x + threadIdx.x) >> 5;
    if (w >= NN) return;
    int lane = threadIdx.x & 31;
    int s0 = g_start[w], s1 = g_start[w + 1];
    float4 ald4 = *(const float4*)&g_ald[w * HH];

    float acc0 = 0, acc1 = 0, acc2 = 0, acc3 = 0;
    float den0 = 0, den1 = 0, den2 = 0, den3 = 0;
    for (int p = s0; p < s1; p++) {
        int src = g_csr_src[p];
        float4 als4 = *(const float4*)&g_als[src * HH];
        float4 ale4 = *(const float4*)&g_ale1[p * HH];
        float a0 = als4.x + ald4.x + ale4.x;
        float a1 = als4.y + ald4.y + ale4.y;
        float a2 = als4.z + ald4.z + ale4.z;
        float a3 = als4.w + ald4.w + ale4.w;
        a0 = (a0 > 0.f) ? a0 : 0.2f * a0;
        a1 = (a1 > 0.f) ? a1 : 0.2f * a1;
        a2 = (a2 > 0.f) ? a2 : 0.2f * a2;
        a3 = (a3 > 0.f) ? a3 : 0.2f * a3;
        float e0 = __expf(a0), e1 = __expf(a1), e2 = __expf(a2), e3 = __expf(a3);
        den0 += e0; den1 += e1; den2 += e2; den3 += e3;
        float xv = (lane < IND) ? __ldg(&x[src * IND + lane]) : 0.0f;
        acc0 += xv * e0; acc1 += xv * e1; acc2 += xv * e2; acc3 += xv * e3;
    }
    float* xa = &g_xa[w * 128];
    xa[lane]      = acc0 / (den0 + 1e-16f);
    xa[32 + lane] = acc1 / (den1 + 1e-16f);
    xa[64 + lane] = acc2 / (den2 + 1e-16f);
    xa[96 + lane] = acc3 / (den3 + 1e-16f);
}

// ---------------- layer-1 post-GEMM: out = relu(xagg @ W1_head + b1) --------
__global__ __launch_bounds__(256) void k_l1post(const float* __restrict__ W1,
                                                const float* __restrict__ b1) {
    __shared__ float xs[32][128];
    int n0 = blockIdx.x * 32;
    int tid = threadIdx.x;
    int head = tid >> 6;
    for (int i = tid; i < 32 * 128; i += 256)
        ((float*)xs)[i] = g_xa[n0 * 128 + i];
    float wr[IND];
#pragma unroll
    for (int c = 0; c < IND; c++) wr[c] = __ldg(&W1[c * HC + tid]);
    float bv = __ldg(&b1[tid]);
    __syncthreads();
#pragma unroll 4
    for (int r = 0; r < 32; r++) {
        int n = n0 + r;
        if (n >= NN) break;
        const float* xr = &xs[r][head * 32];
        float s = bv;
#pragma unroll
        for (int c = 0; c < IND; c++) s += xr[c] * wr[c];
        s = fmaxf(s, 0.0f);
        __nv_bfloat16 hb = __float2bfloat16(s);
        __nv_bfloat16 lb = __float2bfloat16(s - __bfloat162float(hb));
        g_fh[n * HC + tid] = hb;
        g_fl[n * HC + tid] = lb;
    }
}

// ---------------- layer-2 GEMM (WMMA bf16 split) + fused attention dots -----
#define WKC 64
#define LDP 72
#define SM_AH 0
#define SM_AL (128 * LDP)
#define SM_BH (2 * 128 * LDP)
#define SM_BL (2 * 128 * LDP + 256 * LDP)
#define SM_TOT ((2 * 128 * LDP + 2 * 256 * LDP) * 2)   // 110592 bytes

__global__ __launch_bounds__(512) void k_gemm_wmma(const float* __restrict__ a_s,
                                                   const float* __restrict__ a_d) {
    extern __shared__ __nv_bfloat16 sm[];
    int tid = threadIdx.x;
    int wid = tid >> 5;
    int lane = tid & 31;
    int wr = wid >> 2;
    int wc = wid & 3;
    int row0 = blockIdx.x * 128;

    wmma::fragment<wmma::accumulator, 16, 16, 16, float> acc[2][4];
#pragma unroll
    for (int mi = 0; mi < 2; mi++)
#pragma unroll
        for (int ni = 0; ni < 4; ni++) wmma::fill_fragment(acc[mi][ni], 0.0f);

    for (int kc = 0; kc < HC / WKC; kc++) {
        int k0 = kc * WKC;
#pragma unroll
        for (int it = 0; it < 2; it++) {
            int g = tid + it * 512;
            int r = g >> 3, q = g & 7;
            int go = (row0 + r) * HC + k0 + q * 8;
            int so = r * LDP + q * 8;
            *(uint4*)&sm[SM_AH + so] = *(const uint4*)&g_fh[go];
            *(uint4*)&sm[SM_AL + so] = *(const uint4*)&g_fl[go];
        }
#pragma unroll
        for (int it = 0; it < 4; it++) {
            int g = tid + it * 512;
            int r = g >> 3, q = g & 7;
            int go = r * HC + k0 + q * 8;
            int so = r * LDP + q * 8;
            *(uint4*)&sm[SM_BH + so] = *(const uint4*)&g_w2h[go];
            *(uint4*)&sm[SM_BL + so] = *(const uint4*)&g_w2l[go];
        }
        __syncthreads();

#pragma unroll
        for (int ks = 0; ks < WKC / 16; ks++) {
            wmma::fragment<wmma::matrix_a, 16, 16, 16, __nv_bfloat16, wmma::row_major> ah[2], al[2];
            wmma::fragment<wmma::matrix_b, 16, 16, 16, __nv_bfloat16, wmma::col_major> bh[4], bl[4];
#pragma unroll
            for (int mi = 0; mi < 2; mi++) {
                int r = (wr * 32 + mi * 16) * LDP + ks * 16;
                wmma::load_matrix_sync(ah[mi], &sm[SM_AH + r], LDP);
                wmma::load_matrix_sync(al[mi], &sm[SM_AL + r], LDP);
            }
#pragma unroll
            for (int ni = 0; ni < 4; ni++) {
                int r = (wc * 64 + ni * 16) * LDP + ks * 16;
                wmma::load_matrix_sync(bh[ni], &sm[SM_BH + r], LDP);
                wmma::load_matrix_sync(bl[ni], &sm[SM_BL + r], LDP);
            }
#pragma unroll
            for (int mi = 0; mi < 2; mi++)
#pragma unroll
                for (int ni = 0; ni < 4; ni++) {
                    wmma::mma_sync(acc[mi][ni], ah[mi], bh[ni], acc[mi][ni]);
                    wmma::mma_sync(acc[mi][ni], ah[mi], bl[ni], acc[mi][ni]);
                    wmma::mma_sync(acc[mi][ni], al[mi], bh[ni], acc[mi][ni]);
                }
        }
        __syncthreads();
    }
#pragma unroll
    for (int mi = 0; mi < 2; mi++) {
        int row = row0 + wr * 32 + mi * 16;
#pragma unroll
        for (int ni = 0; ni < 4; ni++) {
            int col = wc * 64 + ni * 16;
            wmma::store_matrix_sync(&g_h[row * HC + col], acc[mi][ni], HC,
                                    wmma::mem_row_major);
        }
    }
    // ---- fused attention dots on just-produced rows ----
    __syncthreads();
#pragma unroll 1
    for (int r = 0; r < 8; r++) {
        int node = row0 + wid * 8 + r;
        if (node >= NN) break;
        const float* hr = &g_h[node * HC];
        float ps[4] = {0, 0, 0, 0}, pd[4] = {0, 0, 0, 0};
#pragma unroll
        for (int it = 0; it < 8; it++) {
            int j = lane + 32 * it;
            float hv = hr[j];
            ps[it >> 1] += hv * __ldg(&a_s[j]);
            pd[it >> 1] += hv * __ldg(&a_d[j]);
        }
#pragma unroll
        for (int h = 0; h < HH; h++) {
            float v = ps[h], u = pd[h];
#pragma unroll
            for (int off = 16; off > 0; off >>= 1) {
                v += __shfl_down_sync(0xffffffffu, v, off);
                u += __shfl_down_sync(0xffffffffu, u, off);
            }
            if (lane == 0) {
                g_als[node * HH + h] = v;
                g_ald[node * HH + h] = u;
            }
        }
    }
}

// ---------------- layer-2 single-pass aggregate (warp per node, unroll 2) ---
__global__ __launch_bounds__(256) void k_nodeagg(const float* __restrict__ ale,
                                                 const float* __restrict__ b) {
    int w = (blockIdx.x * blockDim.x + threadIdx.x) >> 5;
    if (w >= NN) return;
    int lane = threadIdx.x & 31;
    int head = lane >> 3;
    int colbase = lane * 8;
    int s0 = g_start[w], s1 = g_start[w + 1];
    float ald_h = __ldg(&g_ald[w * HH + head]);

    float den = 0.0f;
    float acc[8] = {0, 0, 0, 0, 0, 0, 0, 0};
    int p = s0;
    for (; p + 1 < s1; p += 2) {
        int sa = g_csr_src[p];
        int sb = g_csr_src[p + 1];
        const float4* ha = (const float4*)&g_h[sa * HC + colbase];
        const float4* hb = (const float4*)&g_h[sb * HC + colbase];
        float aa = __ldg(&g_als[sa * HH + head]) + ald_h + __ldg(&ale[p * HH + head]);
        float ab = __ldg(&g_als[sb * HH + head]) + ald_h + __ldg(&ale[(p + 1) * HH + head]);
        aa = (aa > 0.0f) ? aa : 0.2f * aa;
        ab = (ab > 0.0f) ? ab : 0.2f * ab;
        float exa = __expf(aa), exb = __expf(ab);
        den += exa + exb;
        float4 a0 = ha[0], a1 = ha[1];
        float4 b0 = hb[0], b1 = hb[1];
        acc[0] += a0.x * exa + b0.x * exb; acc[1] += a0.y * exa + b0.y * exb;
        acc[2] += a0.z * exa + b0.z * exb; acc[3] += a0.w * exa + b0.w * exb;
        acc[4] += a1.x * exa + b1.x * exb; acc[5] += a1.y * exa + b1.y * exb;
        acc[6] += a1.z * exa + b1.z * exb; acc[7] += a1.w * exa + b1.w * exb;
    }
    if (p < s1) {
        int sa = g_csr_src[p];
        const float4* ha = (const float4*)&g_h[sa * HC + colbase];
        float aa = __ldg(&g_als[sa * HH + head]) + ald_h + __ldg(&ale[p * HH + head]);
        aa = (aa > 0.0f) ? aa : 0.2f * aa;
        float exa = __expf(aa);
        den += exa;
        float4 a0 = ha[0], a1 = ha[1];
        acc[0] += a0.x * exa; acc[1] += a0.y * exa;
        acc[2] += a0.z * exa; acc[3] += a0.w * exa;
        acc[4] += a1.x * exa; acc[5] += a1.y * exa;
        acc[6] += a1.z * exa; acc[7] += a1.w * exa;
    }
    float inv = 1.0f / (den + 1e-16f);

    float4 bb0 = __ldg((const float4*)&b[colbase]);
    float4 bb1 = __ldg((const float4*)&b[colbase + 4]);
    float4 o0 = make_float4(fmaxf(acc[0] * inv + bb0.x, 0.f),
                            fmaxf(acc[1] * inv + bb0.y, 0.f),
                            fmaxf(acc[2] * inv + bb0.z, 0.f),
                            fmaxf(acc[3] * inv + bb0.w, 0.f));
    float4 o1 = make_float4(fmaxf(acc[4] * inv + bb1.x, 0.f),
                            fmaxf(acc[5] * inv + bb1.y, 0.f),
                            fmaxf(acc[6] * inv + bb1.z, 0.f),
                            fmaxf(acc[7] * inv + bb1.w, 0.f));
    *(float4*)&g_feat[w * HC + colbase] = o0;
    *(float4*)&g_feat[w * HC + colbase + 4] = o1;
}

// ---------------- fused mean-pool + readout ----------------
__device__ __forceinline__ int lowerb(const int* __restrict__ b, int val) {
    int lo = 0, hi = NN;
    while (lo < hi) {
        int mid = (lo + hi) >> 1;
        if (b[mid] < val) lo = mid + 1; else hi = mid;
    }
    return lo;
}

__global__ __launch_bounds__(256) void k_graph(const int* __restrict__ bat,
                                               const float* __restrict__ Wl,
                                               const float* __restrict__ bl,
                                               float* __restrict__ out) {
    int g = (blockIdx.x * blockDim.x + threadIdx.x) >> 5;
    if (g >= GG) return;
    int lane = threadIdx.x & 31;
    int lo = 0, hi = 0;
    if (lane == 0) {
        lo = lowerb(bat, g);
        hi = lowerb(bat, g + 1);
    }
    lo = __shfl_sync(0xffffffffu, lo, 0);
    hi = __shfl_sync(0xffffffffu, hi, 0);
    float acc[8] = {0, 0, 0, 0, 0, 0, 0, 0};
    int colbase = lane * 8;
    for (int i = lo; i < hi; i++) {
        const float4* fp = (const float4*)&g_feat[i * HC + colbase];
        float4 v0 = fp[0], v1 = fp[1];
        acc[0] += v0.x; acc[1] += v0.y; acc[2] += v0.z; acc[3] += v0.w;
        acc[4] += v1.x; acc[5] += v1.y; acc[6] += v1.z; acc[7] += v1.w;
    }
    float inv = 1.0f / fmaxf((float)(hi - lo), 1.0f);
#pragma unroll
    for (int t = 0; t < NTASK; t++) {
        float p = 0.0f;
#pragma unroll
        for (int k = 0; k < 8; k++)
            p += acc[k] * __ldg(&Wl[(colbase + k) * NTASK + t]);
#pragma unroll
        for (int off = 16; off > 0; off >>= 1)
            p += __shfl_xor_sync(0xffffffffu, p, off);
        if (lane == 0) out[g * NTASK + t] = p * inv + bl[t];
    }
}

// ---------------- host orchestration ----------------
static inline int cdiv(int a, int b) { return (a + b - 1) / b; }

extern "C" void kernel_launch(void* const* d_in, const int* in_sizes, int n_in,
                              void* d_out, int out_size) {
    const float* x   = (const float*)d_in[0];
    const int*   ei  = (const int*)d_in[1];
    const float* ea  = (const float*)d_in[2];
    const int*   bat = (const int*)d_in[3];
    const float* W1  = (const float*)d_in[4];
    const float* as1 = (const float*)d_in[5];
    const float* ad1 = (const float*)d_in[6];
    const float* We1 = (const float*)d_in[7];
    const float* ae1 = (const float*)d_in[8];
    const float* b1  = (const float*)d_in[9];
    const float* W2  = (const float*)d_in[10];
    const float* as2 = (const float*)d_in[11];
    const float* ad2 = (const float*)d_in[12];
    const float* We2 = (const float*)d_in[13];
    const float* ae2 = (const float*)d_in[14];
    const float* b2  = (const float*)d_in[15];
    const float* Wl  = (const float*)d_in[16];
    const float* bl  = (const float*)d_in[17];
    float* out = (float*)d_out;

    static cudaStream_t s2 = nullptr, s3 = nullptr;
    static cudaEvent_t ev_fork = nullptr, ev_aux = nullptr, ev_ve = nullptr;
    if (!s2) {
        cudaStreamCreateWithFlags(&s2, cudaStreamNonBlocking);
        cudaStreamCreateWithFlags(&s3, cudaStreamNonBlocking);
        cudaEventCreateWithFlags(&ev_fork, cudaEventDisableTiming);
        cudaEventCreateWithFlags(&ev_aux, cudaEventDisableTiming);
        cudaEventCreateWithFlags(&ev_ve, cudaEventDisableTiming);
        cudaFuncSetAttribute(k_gemm_wmma,
                             cudaFuncAttributeMaxDynamicSharedMemorySize, SM_TOT);
    }

    float* p_mesum; cudaGetSymbolAddress((void**)&p_mesum, g_mesum);
    int*   p_deg;   cudaGetSymbolAddress((void**)&p_deg, g_deg);
    float* p_ve1;   cudaGetSymbolAddress((void**)&p_ve1, g_ve1);
    float* p_ve2;   cudaGetSymbolAddress((void**)&p_ve2, g_ve2);
    float* p_s1;    cudaGetSymbolAddress((void**)&p_s1, g_self1);
    float* p_s2;    cudaGetSymbolAddress((void**)&p_s2, g_self2);
    float* p_ale1;  cudaGetSymbolAddress((void**)&p_ale1, g_ale1);
    float* p_ale2;  cudaGetSymbolAddress((void**)&p_ale2, g_ale2);

    // ---- fork ----
    cudaEventRecord(ev_fork, 0);
    cudaStreamWaitEvent(s2, ev_fork, 0);
    cudaStreamWaitEvent(s3, ev_fork, 0);

    // s2: W1 attention collapse -> als/ald GEMV; W2 conversion
    k_vsd<<<1, 256, 0, s2>>>(W1, as1, ad1);
    k_alsd<<<cdiv(NN, 32), 256, 0, s2>>>(x);
    k_w2cvt<<<cdiv(HC * HC, 256), 256, 0, s2>>>(W2);
    cudaEventRecord(ev_aux, s2);

    // s3: edge-attr mean -> ve/self for both layers
    k_zero_f<<<1, 256, 0, s3>>>(p_mesum, EDD);
    k_meansum<<<cdiv(MS_N, 256), 256, 0, s3>>>(ea);
    k_ve<<<1, 32, 0, s3>>>(We1, ae1, p_ve1, p_s1);
    k_ve<<<1, 32, 0, s3>>>(We2, ae2, p_ve2, p_s2);
    cudaEventRecord(ev_ve, s3);

    // default: degree count -> scan, then fill (needs ve from s3)
    k_seti<<<cdiv(NN, 256), 256>>>(p_deg, NN, 1);
    k_count<<<cdiv(EE, 256), 256>>>(ei);
    k_scan<<<1, 1024>>>();
    cudaStreamWaitEvent(0, ev_ve, 0);
    k_fill<<<cdiv(ET, 256), 256>>>(ei, ea);
    cudaStreamWaitEvent(0, ev_aux, 0);

    // ---- layer 1: aggregate in x-space, then GEMM ----
    k_nodeagg_x<<<cdiv(NN * 32, 256), 256>>>(x);
    k_l1post<<<cdiv(NN, 32), 256>>>(W1, b1);

    // ---- layer 2 (GEMM with fused att dots) ----
    k_gemm_wmma<<<NP / 128, 512, SM_TOT>>>(as2, ad2);
    k_nodeagg<<<cdiv(NN * 32, 256), 256>>>(p_ale2, b2);

    // ---- readout ----
    k_graph<<<cdiv(GG * 32, 256), 256>>>(bat, Wl, bl, out);
}